// round 6
// baseline (speedup 1.0000x reference)
#include <cuda_runtime.h>
#include <cuda_bf16.h>

typedef unsigned long long ull;

// Problem shapes (fixed)
#define BN 16
#define FN 4096
#define MN 512
#define DN 256
#define VEN 64
#define HN 512
#define OUTN 8
#define VN 50
#define INW 320          // VEN + DN
#define NSEG 8192        // BN * MN

#define NBLK 128
#define NTHR 512
#define TOTW ((NBLK * NTHR) / 32)   // 2048 warps
#define FRPW 16                      // frames per chunk
#define NCHUNK (BN * FN / FRPW)      // 4096
#define CPW (NCHUNK / TOTW)          // 2 chunks per warp (exact)

// ---------------------------------------------------------------------------
// Scratch layout (floats). sum/cnt zeroed in phase 0 by plain stores.
//   sum   [NSEG*8]  @ 0        cnt [NSEG] @ 65536
//   Wf    [2048]    @ 73728    k-major ull view: ull[k*128+jp] = (Wc[64+2jp][k], Wc[64+2jp+1][k])
//   WcEmb [512]     @ 75776    bc [8] @ 76288    pe [400] @ 76296
// ---------------------------------------------------------------------------
#define OFF_SUM   0
#define OFF_CNT   65536
#define OFF_WF    73728
#define OFF_WCEMB 75776
#define OFF_BC    76288
#define OFF_PE    76296
#define SCR_TOTAL 76704

__device__ __align__(16) float g_scr[SCR_TOTAL];
__device__ unsigned g_bar_count = 0;
__device__ unsigned g_bar_sense = 0;   // monotonic generation counter (replay-safe)

__device__ __forceinline__ ull fma2(ull a, ull b, ull c) {
    ull d;
    asm("fma.rn.f32x2 %0, %1, %2, %3;" : "=l"(d) : "l"(a), "l"(b), "l"(c));
    return d;
}
__device__ __forceinline__ ull add2(ull a, ull b) {
    ull d;
    asm("add.rn.f32x2 %0, %1, %2;" : "=l"(d) : "l"(a), "l"(b));
    return d;
}

// ---------------------------------------------------------------------------
// Grid barrier: count + generation sense. Spin compares != target so unsigned
// wraparound across graph replays is harmless.
// ---------------------------------------------------------------------------
__device__ __forceinline__ void grid_barrier(unsigned target) {
    __syncthreads();
    if (threadIdx.x == 0) {
        __threadfence();
        if (atomicAdd(&g_bar_count, 1u) == NBLK - 1) {
            g_bar_count = 0;
            __threadfence();
            atomicAdd(&g_bar_sense, 1u);
        } else {
            while (*(volatile unsigned*)&g_bar_sense != target) __nanosleep(32);
        }
        __threadfence();
    }
    __syncthreads();
}

// ---------------------------------------------------------------------------
// Transposed warp reduction: v[0..7] per lane (k partials) -> each lane
// returns the full warp sum for k = lane & 7. 9 shuffles.
// ---------------------------------------------------------------------------
__device__ __forceinline__ float warp_reduce_k(const float v[8], int lane) {
    const unsigned FULL = 0xFFFFFFFFu;
    float nv[4];
    const int b0 = lane & 1;
#pragma unroll
    for (int i = 0; i < 4; i++) {
        float keep = b0 ? v[2 * i + 1] : v[2 * i];
        float send = b0 ? v[2 * i]     : v[2 * i + 1];
        nv[i] = keep + __shfl_xor_sync(FULL, send, 1);
    }
    const int b1 = (lane >> 1) & 1;
    float mv[2];
#pragma unroll
    for (int i = 0; i < 2; i++) {
        float keep = b1 ? nv[2 * i + 1] : nv[2 * i];
        float send = b1 ? nv[2 * i]     : nv[2 * i + 1];
        mv[i] = keep + __shfl_xor_sync(FULL, send, 2);
    }
    const int b2 = (lane >> 2) & 1;
    float keep = b2 ? mv[1] : mv[0];
    float send = b2 ? mv[0] : mv[1];
    float s = keep + __shfl_xor_sync(FULL, send, 4);
    s += __shfl_xor_sync(FULL, s, 8);
    s += __shfl_xor_sync(FULL, s, 16);
    return s;   // k = lane & 7
}

// ---------------------------------------------------------------------------
// Flush one segment run: project per-lane raw sums (4 f32x2) with smem weights
// (k-major, conflict-free LDS.128), transposed reduce, atomic scatter.
// ---------------------------------------------------------------------------
__device__ __noinline__ void flush_seg(const ull* __restrict__ sWf,
                                       const ull* __restrict__ racc,
                                       float fcnt, int seg, int lane) {
    const int p0 = 2 * lane, p1 = 64 + 2 * lane;
    float v[8];
#pragma unroll
    for (int k = 0; k < 8; k++) {
        ulonglong2 wa = *(const ulonglong2*)(sWf + k * 128 + p0);
        ulonglong2 wb = *(const ulonglong2*)(sWf + k * 128 + p1);
        ull t = fma2(racc[0], wa.x,
                fma2(racc[1], wa.y,
                fma2(racc[2], wb.x,
                fma2(racc[3], wb.y, 0ull))));
        float lo = __int_as_float((int)(t & 0xFFFFFFFFull));
        float hi = __int_as_float((int)(t >> 32));
        v[k] = lo + hi;
    }
    float s = warp_reduce_k(v, lane);
    if (lane < 8) atomicAdd(g_scr + OFF_SUM + seg * OUTN + lane, s);
    else if (lane == 8) atomicAdd(g_scr + OFF_CNT + seg, fcnt);
}

// ---------------------------------------------------------------------------
// Fused persistent kernel: phase0 (zero + fold) | bar | phase1 (proj + pe)
// | bar | phase2 (final).
// ---------------------------------------------------------------------------
__global__ void __launch_bounds__(NTHR) fused_kernel(
    const int* __restrict__ vowels,       // [B, M]
    const float* __restrict__ features,   // [B, F, D]
    const int* __restrict__ mora_index,   // [B, F]
    const float* __restrict__ emb_table,  // [V, VE]
    const float* __restrict__ W_mora,     // [320, 512]
    const float* __restrict__ b_mora,     // [512]
    const float* __restrict__ W_post,     // [512, 8]
    const float* __restrict__ b_post,     // [8]
    float* __restrict__ out)              // [B, M, 8]
{
    __shared__ __align__(16) ull sWf[128 * 8];   // 8 KB
    const unsigned FULL = 0xFFFFFFFFu;
    const int tid = threadIdx.x;
    const int lane = tid & 31;
    const int gthr = blockIdx.x * NTHR + tid;
    const int gw = gthr >> 5;                 // global warp 0..2047

    // read barrier generation before any barrier can release (safe: release
    // requires all blocks to arrive, and we read before arriving)
    const unsigned bar_base = *(volatile unsigned*)&g_bar_sense;

    // ================= phase 0: zero accumulators + fold =================
    {
        float4 z = make_float4(0.f, 0.f, 0.f, 0.f);
        for (int j = gthr; j < (OFF_CNT + NSEG) / 4; j += NBLK * NTHR)
            ((float4*)g_scr)[j] = z;
    }

    if (gw <= INW) {
        // warp gw folds row gw of Wc (gw==INW -> bias row)
        const float* src = (gw < INW) ? (W_mora + (size_t)gw * HN) : b_mora;
        float acc[8];
#pragma unroll
        for (int k = 0; k < 8; k++) acc[k] = 0.0f;
#pragma unroll
        for (int j = 0; j < 16; j++) {
            const int h = 32 * j + lane;
            const float a = src[h];
            const float4* wp = (const float4*)(W_post + h * OUTN);
            float4 p0 = wp[0], p1 = wp[1];
            acc[0] += a * p0.x; acc[1] += a * p0.y; acc[2] += a * p0.z; acc[3] += a * p0.w;
            acc[4] += a * p1.x; acc[5] += a * p1.y; acc[6] += a * p1.z; acc[7] += a * p1.w;
        }
        float s = warp_reduce_k(acc, lane);
        if (lane < 8) {
            const int k = lane;
            if (gw < VEN) {
                g_scr[OFF_WCEMB + gw * OUTN + k] = s;
            } else if (gw < INW) {
                const int j = gw - VEN;
                g_scr[OFF_WF + (k * 128 + (j >> 1)) * 2 + (j & 1)] = s;
            } else {
                g_scr[OFF_BC + k] = s + b_post[k];
            }
        }
    }

    grid_barrier(bar_base + 1);

    // ================= phase 1: pe + stage weights + proj =================
    if (blockIdx.x == NBLK - 1 && tid < VN * OUTN) {
        // per-vowel embedding projection: pe[v][k] = emb[v] . WcEmb[:,k]
        const int v = tid >> 3, k = tid & 7;
        const float* e = emb_table + v * VEN;
        float s = 0.0f;
#pragma unroll 8
        for (int j = 0; j < VEN; j++)
            s += e[j] * __ldcg(g_scr + OFF_WCEMB + j * OUTN + k);
        g_scr[OFF_PE + tid] = s;
    }

    {
        const float4* src4 = (const float4*)(g_scr + OFF_WF);   // 512 float4
        float4* dst4 = (float4*)sWf;
        if (tid < 512) dst4[tid] = __ldcg(src4 + tid);
    }
    __syncthreads();

#pragma unroll
    for (int c = 0; c < CPW; c++) {
        const int chunk = gw + c * TOTW;
        const int basef = chunk * FRPW;       // 16 contiguous frames, same b
        const int b = basef >> 12;            // / FN
        const int myidx = mora_index[basef + (lane & 15)];

        ull racc[4];
#pragma unroll
        for (int q = 0; q < 4; q++) racc[q] = 0ull;
        float fcnt = 0.0f;
        int curm = __shfl_sync(FULL, myidx, 0);

        const ulonglong2* fr = (const ulonglong2*)(features + (size_t)basef * DN);

#pragma unroll
        for (int it0 = 0; it0 < FRPW; it0 += 4) {
            // batch loads: 8 back-to-back LDG.128
            ulonglong2 xa[4], xb[4];
#pragma unroll
            for (int j = 0; j < 4; j++) {
                xa[j] = fr[(it0 + j) * 64 + lane];        // dims 4l..4l+3
                xb[j] = fr[(it0 + j) * 64 + 32 + lane];   // dims 128+4l..
            }
#pragma unroll
            for (int j = 0; j < 4; j++) {
                const int m = __shfl_sync(FULL, myidx, it0 + j);
                if (m != curm) {                          // warp-uniform
                    flush_seg(sWf, racc, fcnt, (b << 9) + curm, lane);
#pragma unroll
                    for (int q = 0; q < 4; q++) racc[q] = 0ull;
                    fcnt = 0.0f;
                    curm = m;
                }
                racc[0] = add2(racc[0], xa[j].x);
                racc[1] = add2(racc[1], xa[j].y);
                racc[2] = add2(racc[2], xb[j].x);
                racc[3] = add2(racc[3], xb[j].y);
                fcnt += 1.0f;
            }
        }
        flush_seg(sWf, racc, fcnt, (b << 9) + curm, lane);
    }

    grid_barrier(bar_base + 2);

    // ================= phase 2: finalize =================
    if (gthr < NSEG) {
        const int row = gthr;
        const int v = vowels[row];
        const float4 b0 = __ldcg((const float4*)(g_scr + OFF_BC));
        const float4 b1 = __ldcg((const float4*)(g_scr + OFF_BC) + 1);
        const float4 p0 = __ldcg((const float4*)(g_scr + OFF_PE) + v * 2);
        const float4 p1 = __ldcg((const float4*)(g_scr + OFF_PE) + v * 2 + 1);
        const float4 s0 = __ldcg((const float4*)(g_scr + OFF_SUM) + row * 2);
        const float4 s1 = __ldcg((const float4*)(g_scr + OFF_SUM) + row * 2 + 1);
        const float cnt = __ldcg(g_scr + OFF_CNT + row);
        const float inv = (cnt > 0.0f) ? (1.0f / cnt) : 0.0f;

        float4 o0, o1;
        o0.x = b0.x + p0.x + s0.x * inv; o0.y = b0.y + p0.y + s0.y * inv;
        o0.z = b0.z + p0.z + s0.z * inv; o0.w = b0.w + p0.w + s0.w * inv;
        o1.x = b1.x + p1.x + s1.x * inv; o1.y = b1.y + p1.y + s1.y * inv;
        o1.z = b1.z + p1.z + s1.z * inv; o1.w = b1.w + p1.w + s1.w * inv;

        ((float4*)out)[row * 2]     = o0;
        ((float4*)out)[row * 2 + 1] = o1;
    }
}

// ---------------------------------------------------------------------------
// launch: single persistent kernel, single graph node
// ---------------------------------------------------------------------------
extern "C" void kernel_launch(void* const* d_in, const int* in_sizes, int n_in,
                              void* d_out, int out_size)
{
    const int*   vowels     = (const int*)d_in[0];
    const float* features   = (const float*)d_in[1];
    const int*   mora_index = (const int*)d_in[2];
    const float* emb_table  = (const float*)d_in[3];
    const float* W_mora     = (const float*)d_in[4];
    const float* b_mora     = (const float*)d_in[5];
    // d_in[6] = W_frame, d_in[7] = b_frame: dead branch, unused
    const float* W_post     = (const float*)d_in[8];
    const float* b_post     = (const float*)d_in[9];
    float* out = (float*)d_out;

    fused_kernel<<<NBLK, NTHR>>>(vowels, features, mora_index, emb_table,
                                 W_mora, b_mora, W_post, b_post, out);
}